// round 6
// baseline (speedup 1.0000x reference)
#include <cuda_runtime.h>
#include <cstdint>

// Problem geometry (fixed by the reference).
#define NCELLS (32 * 256 * 128)      // El*R*Az = 1,048,576 polar cells per batch
#define NVOX   (320 * 320 * 80)      // 8,192,000 voxels per batch
#define BATCH  16
#define FULLM  0xffffffffu

#define ZERO_BLOCKS 1184u            // 8 CTAs/SM x 148 SMs: one resident wave
#define OUT_BYTES   (16ull * NVOX * 4ull)          // 524,288,000
#define N32         (OUT_BYTES / 32ull)            // 16,384,000 x 32B stores

// ---------------------------------------------------------------------------
// Zero kernel: 256-bit stores, grid-stride, full 128B-line coverage per warp
// (no write-allocate reads). Targets DRAM write ceiling (~7.5 TB/s).
__global__ void __launch_bounds__(256)
zero_out(float* __restrict__ out)
{
    unsigned long long t      = blockIdx.x * 256ull + threadIdx.x;
    unsigned long long stride = ZERO_BLOCKS * 256ull;
    for (; t < N32; t += stride) {
        float* p = out + t * 8ull;
        asm volatile(
            "st.global.v8.f32 [%0], {%1,%1,%1,%1,%1,%1,%1,%1};"
            :: "l"(p), "f"(0.0f) : "memory");
    }
}

// ---------------------------------------------------------------------------
// Scatter (R5 structure, verified): one warp = az-rows (r, r+1) of one el.
// Lane t takes cells base + t + 32j, so each round holds 32 CONTIGUOUS az
// cells. Radial pair-merge in registers, then per-round segmented warp scan;
// one RED per run, emitted by the run's last lane; all-merged runs skip.
// Deep (depth-5) scan only needed where runs can exceed 16 lanes: r < 1m,
// i.e. rows 0..15 -> blocks with blockIdx.x % 16 == 0.
__global__ void __launch_bounds__(256)
polar_scatter_agg(const float* __restrict__ in,
                  const int*   __restrict__ idx,
                  float*       __restrict__ out)
{
    unsigned warp = threadIdx.x >> 5;                  // 0..7
    unsigned lane = threadIdx.x & 31u;
    unsigned b    = blockIdx.y;
    unsigned base = (blockIdx.x * 8u + warp) * 256u;   // gridDim.x = 512
    bool     deep = (blockIdx.x & 15u) == 0u;          // rows 0..15 of an el

    const float* pin = in + (size_t)b * NCELLS;
    float*       ob  = out + (size_t)b * NVOX;

    int   v[8];
    float x[8];
#pragma unroll
    for (int j = 0; j < 8; j++) {
        unsigned c = base + lane + 32u * j;            // coalesced 128B/round
        v[j] = idx[c];
        x[j] = pin[c];
    }

    // Radial pair-merge: round j (row r) vs j+4 (row r+1), same az chunk.
#pragma unroll
    for (int j = 0; j < 4; j++) {
        if (v[j] == v[j + 4]) { x[j] += x[j + 4]; x[j + 4] = 0.f; }
    }

#pragma unroll
    for (int j = 0; j < 8; j++) {
        int   vv = v[j];
        float s  = x[j];

        int  prev = __shfl_up_sync(FULLM, vv, 1);
        bool head = (lane == 0) || (prev != vv);
        unsigned hmask = __ballot_sync(FULLM, head);

        // start lane of this lane's run = highest head bit <= lane
        unsigned below = hmask & (0xffffffffu >> (31u - lane));
        int seg = 31 - __clz(below);

        // segmented inclusive scan of s within the run (depth 4 suffices for
        // runs <= 16; depth 5 only in the near-origin blocks)
#pragma unroll
        for (int off = 1; off < 16; off <<= 1) {
            float t = __shfl_up_sync(FULLM, s, off);
            if ((int)lane - off >= seg) s += t;
        }
        if (deep) {
            float t = __shfl_up_sync(FULLM, s, 16);
            if ((int)lane - 16 >= seg) s += t;
        }

        bool last = (lane == 31) || ((hmask >> (lane + 1)) & 1u);
        if (last && s != 0.f)                  // s==0 <=> fully merged run
            atomicAdd(ob + vv, s);             // no return -> REDG
    }
}

extern "C" void kernel_launch(void* const* d_in, const int* in_sizes, int n_in,
                              void* d_out, int out_size)
{
    const float* polar = (const float*)d_in[0];   // [16,1,32,256,128] f32
    const int*   idx   = (const int*)  d_in[1];   // [1048576] int32
    float*       out   = (float*)d_out;           // [16,1,80,320,320] f32

    // Phase 1: zero the 524MB output (DRAM-write bound). Overlap with the
    // scatter is provably useless here (measured additive twice).
    zero_out<<<ZERO_BLOCKS, 256>>>(out);

    // Phase 2: aggregated atomic scatter.
    dim3 grid(512, BATCH);
    polar_scatter_agg<<<grid, 256>>>(polar, idx, out);
}

// round 10
// speedup vs baseline: 1.0151x; 1.0151x over previous
#include <cuda_runtime.h>

// Problem geometry (fixed by the reference).
#define NCELLS (32 * 256 * 128)      // El*R*Az = 1,048,576 polar cells per batch
#define NVOX   (320 * 320 * 80)      // 8,192,000 voxels per batch
#define BATCH  16
#define BPG    4                     // batches per block (grid.y = 16/BPG)
#define FULLM  0xffffffffu

// Scatter (R5-verified structure + batch amortization):
// One warp owns the az-rows (r, r+1) of one el (256 contiguous cells); lane t
// takes cells base + t + 32j, so round j covers 32 CONTIGUOUS az cells and
// equal voxel indices form contiguous lane runs.
//   - voxel indices and the full run structure (segment starts, run-last
//     flags, radial pair-merge mask) are batch-invariant: computed ONCE,
//     reused for BPG batches. Boolean state packed into bitmasks to keep
//     register pressure (and occupancy) close to the R5 kernel.
//   - per batch: coalesced value load, radial pair-merge (rows r/r+1 are
//     0.125m apart vs 0.25m voxels -> ~50% same voxel), masked segmented
//     warp scan, one RED per run emitted by the run's last lane. Runs whose
//     sum is exactly 0 (fully merged) skip the RED.
__global__ void __launch_bounds__(256)
polar_scatter_agg(const float* __restrict__ in,
                  const int*   __restrict__ idx,
                  float*       __restrict__ out)
{
    unsigned warp = threadIdx.x >> 5;                  // 0..7
    unsigned lane = threadIdx.x & 31u;
    unsigned base = (blockIdx.x * 8u + warp) * 256u;   // gridDim.x = 512

    // ---- batch-invariant part -------------------------------------------
    int v[8];
#pragma unroll
    for (int j = 0; j < 8; j++)
        v[j] = idx[base + lane + 32u * j];             // coalesced 128B/round

    unsigned mmask = 0;                                // radial pair-merge bits
#pragma unroll
    for (int j = 0; j < 4; j++)
        if (v[j] == v[j + 4]) mmask |= 1u << j;

    int      seg[8];                                   // run start lane
    unsigned lmask = 0;                                // run-last bits
#pragma unroll
    for (int j = 0; j < 8; j++) {
        int  prev = __shfl_up_sync(FULLM, v[j], 1);
        bool head = (lane == 0) || (prev != v[j]);
        unsigned hmask = __ballot_sync(FULLM, head);
        unsigned below = hmask & (0xffffffffu >> (31u - lane));
        seg[j] = 31 - __clz(below);
        if ((lane == 31) || ((hmask >> (lane + 1)) & 1u)) lmask |= 1u << j;
    }

    // ---- per-batch part --------------------------------------------------
    unsigned b0 = blockIdx.y * BPG;
#pragma unroll
    for (unsigned bb = 0; bb < BPG; bb++) {
        unsigned b = b0 + bb;
        const float* pin = in + (size_t)b * NCELLS + base + lane;
        float*       ob  = out + (size_t)b * NVOX;

        float x[8];
#pragma unroll
        for (int j = 0; j < 8; j++)
            x[j] = pin[32u * j];

#pragma unroll
        for (int j = 0; j < 4; j++)
            if ((mmask >> j) & 1u) { x[j] += x[j + 4]; x[j + 4] = 0.f; }

#pragma unroll
        for (int j = 0; j < 8; j++) {
            float s = x[j];
            // segmented inclusive scan within the (precomputed) run
#pragma unroll
            for (int off = 1; off < 32; off <<= 1) {
                float t = __shfl_up_sync(FULLM, s, off);
                if ((int)lane - off >= seg[j]) s += t;
            }
            if (((lmask >> j) & 1u) && s != 0.f)   // s==0 <=> fully merged
                atomicAdd(ob + v[j], s);           // no return -> REDG
        }
    }
}

extern "C" void kernel_launch(void* const* d_in, const int* in_sizes, int n_in,
                              void* d_out, int out_size)
{
    const float* polar = (const float*)d_in[0];   // [16,1,32,256,128] f32
    const int*   idx   = (const int*)  d_in[1];   // [1048576] int32
    float*       out   = (float*)d_out;           // [16,1,80,320,320] f32

    // Phase 1: zero the 524MB output. Driver memset is the fastest measured
    // writer (6.6 TB/s); custom store kernels and overlap schemes both lost.
    cudaMemsetAsync(d_out, 0, (size_t)out_size * sizeof(float));

    // Phase 2: aggregated atomic scatter, run-structure amortized 4x.
    dim3 grid(512, BATCH / BPG);
    polar_scatter_agg<<<grid, 256>>>(polar, idx, out);
}

// round 11
// speedup vs baseline: 1.0460x; 1.0304x over previous
#include <cuda_runtime.h>

// Problem geometry (fixed by the reference).
#define NCELLS (32 * 256 * 128)      // El*R*Az = 1,048,576 polar cells per batch
#define NVOX   (320 * 320 * 80)      // 8,192,000 voxels per batch
#define BATCH  16
#define BPG    4                     // batches per block (grid.y = 16/BPG)
#define FULLM  0xffffffffu

// Scatter, R5-verified mapping + register-frugal batch amortization.
// One warp owns az-rows (r, r+1) of one el (256 contiguous cells); lane t
// takes cells base + t + 32j, so each round holds 32 CONTIGUOUS az cells and
// equal voxel indices form contiguous lane runs.
//
// R10 lesson: holding all 8 rounds' run structure across the batch loop blew
// registers to 84 and collapsed occupancy (23.6%). Fix: outer loop over the 4
// radial PAIRS (j, j+4); only that pair's structure (2 idx, 2 seg, 3 preds)
// is live while the inner 4-batch loop runs. ~30 regs -> full occupancy, and
// idx loads + head-ballot work still amortized 4x. RED count unchanged.
__global__ void __launch_bounds__(256)
polar_scatter_agg(const float* __restrict__ in,
                  const int*   __restrict__ idx,
                  float*       __restrict__ out)
{
    unsigned warp = threadIdx.x >> 5;                  // 0..7
    unsigned lane = threadIdx.x & 31u;
    unsigned base = (blockIdx.x * 8u + warp) * 256u;   // gridDim.x = 512
    unsigned b0   = blockIdx.y * BPG;

    const unsigned lanebit_ge = 0xffffffffu >> (31u - lane);

#pragma unroll
    for (int j = 0; j < 4; j++) {
        // ---- batch-invariant structure for radial pair (j, j+4) ----------
        int vA = idx[base + lane + 32u * j];           // row r   (coalesced)
        int vB = idx[base + lane + 32u * (j + 4)];     // row r+1 (coalesced)
        bool merge = (vA == vB);                       // 0.125m step vs 0.25m voxel

        int pA = __shfl_up_sync(FULLM, vA, 1);
        unsigned hA = __ballot_sync(FULLM, (lane == 0) || (pA != vA));
        int segA = 31 - __clz(hA & lanebit_ge);
        bool lastA = (lane == 31) || ((hA >> (lane + 1)) & 1u);

        int pB = __shfl_up_sync(FULLM, vB, 1);
        unsigned hB = __ballot_sync(FULLM, (lane == 0) || (pB != vB));
        int segB = 31 - __clz(hB & lanebit_ge);
        bool lastB = (lane == 31) || ((hB >> (lane + 1)) & 1u);

        // ---- per-batch work ----------------------------------------------
#pragma unroll
        for (unsigned bb = 0; bb < BPG; bb++) {
            unsigned b = b0 + bb;
            const float* pin = in + (size_t)b * NCELLS + base + lane;
            float*       ob  = out + (size_t)b * NVOX;

            float xA = pin[32u * j];
            float xB = pin[32u * (j + 4)];
            if (merge) { xA += xB; xB = 0.f; }

            // segmented inclusive scan of xA within its run
#pragma unroll
            for (int off = 1; off < 32; off <<= 1) {
                float t = __shfl_up_sync(FULLM, xA, off);
                if ((int)lane - off >= segA) xA += t;
            }
            if (lastA && xA != 0.f)
                atomicAdd(ob + vA, xA);                // no return -> REDG

            // segmented inclusive scan of xB within its run
#pragma unroll
            for (int off = 1; off < 32; off <<= 1) {
                float t = __shfl_up_sync(FULLM, xB, off);
                if ((int)lane - off >= segB) xB += t;
            }
            if (lastB && xB != 0.f)                    // 0 <=> fully merged
                atomicAdd(ob + vB, xB);
        }
    }
}

extern "C" void kernel_launch(void* const* d_in, const int* in_sizes, int n_in,
                              void* d_out, int out_size)
{
    const float* polar = (const float*)d_in[0];   // [16,1,32,256,128] f32
    const int*   idx   = (const int*)  d_in[1];   // [1048576] int32
    float*       out   = (float*)d_out;           // [16,1,80,320,320] f32

    // Phase 1: zero the 524MB output. Driver memset is the fastest measured
    // writer (6.6 TB/s); custom store kernels and overlap schemes both lost.
    cudaMemsetAsync(d_out, 0, (size_t)out_size * sizeof(float));

    // Phase 2: aggregated atomic scatter, run-structure amortized 4x with
    // only one radial pair's state live at a time.
    dim3 grid(512, BATCH / BPG);
    polar_scatter_agg<<<grid, 256>>>(polar, idx, out);
}

// round 13
// speedup vs baseline: 1.0769x; 1.0296x over previous
#include <cuda_runtime.h>

// Problem geometry (fixed by the reference).
#define NCELLS (32 * 256 * 128)      // El*R*Az = 1,048,576 polar cells per batch
#define NVOX   (320 * 320 * 80)      // 8,192,000 voxels per batch
#define BATCH  16
#define FULLM  0xffffffffu

// Scatter: R5-verified per-batch structure, radial merge widened to 4 rows.
// One warp owns 4 consecutive az-rows (r..r+3) of one el = 512 cells.
// For az-chunk c (0..3), lanes hold 32 CONTIGUOUS az cells of each row:
//   1) radial chain-merge: the 4 same-az cells at rows r..r+3 walk
//      monotonically through the grid (0.125m steps vs 0.25m voxels), so
//      equal voxel indices are consecutive; fold chains into their first
//      cell (exact). Catches the misaligned pairs (1,2) and (2,3) that the
//      R5 2-row pairing missed (~40% of radial merges recovered).
//   2) per-row segmented warp scan over the 32 contiguous az cells: one RED
//      per run of equal index, emitted by the run's last lane; runs whose
//      sum is exactly 0 (fully merged) skip the RED.
__global__ void __launch_bounds__(256)
polar_scatter_agg(const float* __restrict__ in,
                  const int*   __restrict__ idx,
                  float*       __restrict__ out)
{
    unsigned warp = threadIdx.x >> 5;                  // 0..7
    unsigned lane = threadIdx.x & 31u;
    unsigned b    = blockIdx.y;
    unsigned base = (blockIdx.x * 8u + warp) * 512u;   // gridDim.x = 256

    const float* pin = in + (size_t)b * NCELLS;
    float*       ob  = out + (size_t)b * NVOX;
    const unsigned lanebit_ge = 0xffffffffu >> (31u - lane);

#pragma unroll
    for (int c = 0; c < 4; c++) {                      // az chunk
        unsigned cb = base + (unsigned)c * 32u + lane;

        int   v[4];
        float x[4];
#pragma unroll
        for (int k = 0; k < 4; k++) {                  // radial rows r..r+3
            v[k] = idx[cb + 128u * k];                 // coalesced 128B
            x[k] = pin[cb + 128u * k];
        }

        // radial chain-merge (exact: equal indices are consecutive along r)
        {
            int t = 0;
#pragma unroll
            for (int k = 1; k < 4; k++) {
                if (v[k] == v[t]) { x[t] += x[k]; x[k] = 0.f; }
                else               t = k;
            }
        }

        // per-row segmented scan + one RED per run
#pragma unroll
        for (int k = 0; k < 4; k++) {
            int   vv = v[k];
            float s  = x[k];

            int  prev = __shfl_up_sync(FULLM, vv, 1);
            bool head = (lane == 0) || (prev != vv);
            unsigned hmask = __ballot_sync(FULLM, head);
            int seg = 31 - __clz(hmask & lanebit_ge);

#pragma unroll
            for (int off = 1; off < 32; off <<= 1) {
                float t = __shfl_up_sync(FULLM, s, off);
                if ((int)lane - off >= seg) s += t;
            }

            bool last = (lane == 31) || ((hmask >> (lane + 1)) & 1u);
            if (last && s != 0.f)                  // s==0 <=> fully merged
                atomicAdd(ob + vv, s);             // no return -> REDG
        }
    }
}

extern "C" void kernel_launch(void* const* d_in, const int* in_sizes, int n_in,
                              void* d_out, int out_size)
{
    const float* polar = (const float*)d_in[0];   // [16,1,32,256,128] f32
    const int*   idx   = (const int*)  d_in[1];   // [1048576] int32
    float*       out   = (float*)d_out;           // [16,1,80,320,320] f32

    // Phase 1: zero the 524MB output. Driver memset is the fastest measured
    // writer (6.6 TB/s); custom store kernels and overlap schemes all lost.
    cudaMemsetAsync(d_out, 0, (size_t)out_size * sizeof(float));

    // Phase 2: aggregated atomic scatter, per-batch (batch-amortization lost
    // twice), 4-row radial chain merge.
    dim3 grid(256, BATCH);
    polar_scatter_agg<<<grid, 256>>>(polar, idx, out);
}